// round 3
// baseline (speedup 1.0000x reference)
#include <cuda_runtime.h>
#include <cstdint>
#include <cstddef>

#define HD 1024
#define BA 64
#define TS 256
#define NL 4
#define MR (BA*TS)
#define NCTA 128
#define NFEAT 8

// ---------------- device scratch (no allocations allowed) ----------------
__device__ float    g_A[(size_t)MR * HD];
__device__ float    g_X[(size_t)MR * HD];
__device__ float    g_h[BA * HD];
__device__ float2   g_st[NCTA][BA];
__device__ unsigned g_bar;

typedef unsigned long long ull;

__device__ __forceinline__ void fma2(ull& d, ull a, ull b) {
    asm volatile("fma.rn.f32x2 %0, %1, %2, %0;" : "+l"(d) : "l"(a), "l"(b));
}
__device__ __forceinline__ ull splat(float x) {
    ull d; asm("mov.b64 %0, {%1, %1};" : "=l"(d) : "f"(x)); return d;
}
__device__ __forceinline__ float2 unpk(ull v) {
    float2 r; asm("mov.b64 {%0, %1}, %2;" : "=f"(r.x), "=f"(r.y) : "l"(v)); return r;
}
__device__ __forceinline__ unsigned ldacq(unsigned* p) {
    unsigned v; asm volatile("ld.acquire.gpu.u32 %0, [%1];" : "=r"(v) : "l"(p)); return v;
}
__device__ __forceinline__ void redrel(unsigned* p) {
    asm volatile("red.release.gpu.global.add.u32 [%0], 1;" :: "l"(p));
}

// =====================================================================
// GEMM: out[m][n] = sum_k X[m][k]*W[n][k] + bias[n];  M=16384, N=K=1024
// =====================================================================
__global__ __launch_bounds__(256, 2) void gemm_f2(
    const float* __restrict__ X, const float* __restrict__ W,
    const float* __restrict__ bias, float* __restrict__ out)
{
    __shared__ float sA[2][8][128];
    __shared__ float sB[2][8][128];
    const int tid = threadIdx.x;
    const int r = tid >> 1, hf = tid & 1;     // stage: row, k-half
    const int ty = tid >> 4, tx = tid & 15;   // compute: 16x16 threads, 8x8 each

    const float* xp = X + (size_t)(blockIdx.y * 128 + r) * HD + hf * 4;
    const float* wp = W + (size_t)(blockIdx.x * 128 + r) * HD + hf * 4;

    ull acc[8][4];
    #pragma unroll
    for (int i = 0; i < 8; i++)
        #pragma unroll
        for (int j = 0; j < 4; j++) acc[i][j] = 0ull;

    float4 xa = *(const float4*)xp;
    float4 wa = *(const float4*)wp;
    // stage buffer 0
    {
        int kb = hf * 4;
        sA[0][kb+0][r] = xa.x; sA[0][kb+1][r] = xa.y; sA[0][kb+2][r] = xa.z; sA[0][kb+3][r] = xa.w;
        sB[0][kb+0][r] = wa.x; sB[0][kb+1][r] = wa.y; sB[0][kb+2][r] = wa.z; sB[0][kb+3][r] = wa.w;
    }
    __syncthreads();

    for (int c = 0; c < 128; c++) {
        const int cur = c & 1;
        if (c < 127) {
            xa = *(const float4*)(xp + (size_t)(c + 1) * 8);
            wa = *(const float4*)(wp + (size_t)(c + 1) * 8);
        }
        #pragma unroll
        for (int k = 0; k < 8; k++) {
            float4 a0 = *(const float4*)&sA[cur][k][ty * 8];
            float4 a1 = *(const float4*)&sA[cur][k][ty * 8 + 4];
            ulonglong2 b0 = *(const ulonglong2*)&sB[cur][k][tx * 8];
            ulonglong2 b1 = *(const ulonglong2*)&sB[cur][k][tx * 8 + 4];
            ull as[8] = { splat(a0.x), splat(a0.y), splat(a0.z), splat(a0.w),
                          splat(a1.x), splat(a1.y), splat(a1.z), splat(a1.w) };
            #pragma unroll
            for (int i = 0; i < 8; i++) {
                fma2(acc[i][0], as[i], b0.x);
                fma2(acc[i][1], as[i], b0.y);
                fma2(acc[i][2], as[i], b1.x);
                fma2(acc[i][3], as[i], b1.y);
            }
        }
        if (c < 127) {
            int kb = hf * 4;
            int nb = cur ^ 1;
            sA[nb][kb+0][r] = xa.x; sA[nb][kb+1][r] = xa.y; sA[nb][kb+2][r] = xa.z; sA[nb][kb+3][r] = xa.w;
            sB[nb][kb+0][r] = wa.x; sB[nb][kb+1][r] = wa.y; sB[nb][kb+2][r] = wa.z; sB[nb][kb+3][r] = wa.w;
        }
        __syncthreads();
    }

    const size_t m0 = (size_t)blockIdx.y * 128 + ty * 8;
    const int n0 = blockIdx.x * 128 + tx * 8;
    float bl[8];
    #pragma unroll
    for (int j = 0; j < 8; j++) bl[j] = __ldg(bias + n0 + j);
    #pragma unroll
    for (int i = 0; i < 8; i++) {
        float2 p0 = unpk(acc[i][0]), p1 = unpk(acc[i][1]);
        float2 p2 = unpk(acc[i][2]), p3 = unpk(acc[i][3]);
        float4 o0 = make_float4(p0.x + bl[0], p0.y + bl[1], p1.x + bl[2], p1.y + bl[3]);
        float4 o1 = make_float4(p2.x + bl[4], p2.y + bl[5], p3.x + bl[6], p3.y + bl[7]);
        *(float4*)&out[(m0 + i) * HD + n0]     = o0;
        *(float4*)&out[(m0 + i) * HD + n0 + 4] = o1;
    }
}

// =====================================================================
// Persistent recurrence: 128 CTAs x 256 thr, CTA owns 8 features.
// thread: b = tid>>2, ph = (tid>>1)&1 (feature quad), kh = tid&1 (K half)
// =====================================================================
__global__ void rst_bar() { g_bar = 0u; }

__global__ __launch_bounds__(256, 1) void recur(
    const float* __restrict__ A, const float* __restrict__ Wh,
    const float* __restrict__ lng, const float* __restrict__ lnb,
    float* __restrict__ xout)
{
    __shared__ float Ws[HD * NFEAT];                 // [k][8] = 32 KB
    __shared__ float s_mu[BA], s_rs[BA], s_g[NFEAT], s_b[NFEAT];

    const int tid = threadIdx.x, cta = blockIdx.x;
    const int n0 = cta * NFEAT;
    const int kh = tid & 1, ph = (tid >> 1) & 1, b = tid >> 2;

    for (int i = tid; i < HD * NFEAT; i += 256) {
        int k = i >> 3, f = i & 7;
        Ws[i] = Wh[(size_t)(n0 + f) * HD + k];
    }
    if (tid < NFEAT) { s_g[tid] = lng[n0 + tid]; s_b[tid] = lnb[n0 + tid]; }
    for (int i = tid; i < BA * 2; i += 256) {        // zero our h slice
        int bb = i >> 1, half = i & 1;
        __stcg((float4*)&g_h[bb * HD + n0 + half * 4], make_float4(0.f, 0.f, 0.f, 0.f));
    }
    __syncthreads();

    unsigned tgt = 0;
    auto gbar = [&]() {
        __syncthreads();
        tgt += NCTA;
        if (tid == 0) {
            redrel(&g_bar);
            while (ldacq(&g_bar) < tgt) { }
        }
        __syncthreads();
    };
    gbar();                                          // h zero visible everywhere

    const float* hp0 = g_h + (size_t)b * HD + kh * 512;
    const float* wsp = Ws + (size_t)(kh * 512) * 8 + ph * 4;

    for (int t = 0; t < TS; t++) {
        ull a0 = 0ull, a1 = 0ull;
        #pragma unroll 8
        for (int k = 0; k < 512; k += 4) {
            float4 hv = __ldcg((const float4*)(hp0 + k));
            ulonglong2 w0 = *(const ulonglong2*)(wsp + (size_t)(k + 0) * 8);
            ulonglong2 w1 = *(const ulonglong2*)(wsp + (size_t)(k + 1) * 8);
            ulonglong2 w2 = *(const ulonglong2*)(wsp + (size_t)(k + 2) * 8);
            ulonglong2 w3 = *(const ulonglong2*)(wsp + (size_t)(k + 3) * 8);
            ull s0 = splat(hv.x), s1 = splat(hv.y), s2 = splat(hv.z), s3 = splat(hv.w);
            fma2(a0, s0, w0.x); fma2(a1, s0, w0.y);
            fma2(a0, s1, w1.x); fma2(a1, s1, w1.y);
            fma2(a0, s2, w2.x); fma2(a1, s2, w2.y);
            fma2(a0, s3, w3.x); fma2(a1, s3, w3.y);
        }
        // combine K halves (both kh lanes end with full dot)
        {
            ull o0 = __shfl_xor_sync(0xffffffffu, a0, 1);
            ull o1 = __shfl_xor_sync(0xffffffffu, a1, 1);
            asm volatile("add.rn.f32x2 %0, %0, %1;" : "+l"(a0) : "l"(o0));
            asm volatile("add.rn.f32x2 %0, %0, %1;" : "+l"(a1) : "l"(o1));
        }
        float4 av = *(const float4*)(A + ((size_t)b * TS + t) * HD + n0 + ph * 4);
        float2 z01 = unpk(a0), z23 = unpk(a1);
        z01.x += av.x; z01.y += av.y; z23.x += av.z; z23.y += av.w;

        float s = z01.x + z01.y + z23.x + z23.y;
        float q = z01.x * z01.x + z01.y * z01.y + z23.x * z23.x + z23.y * z23.y;
        s += __shfl_xor_sync(0xffffffffu, s, 2);
        q += __shfl_xor_sync(0xffffffffu, q, 2);
        if ((tid & 3) == 0) __stcg((float2*)&g_st[cta][b], make_float2(s, q));
        gbar();                                      // stats ready

        {   // reduce 128 partials: thread (rb, rq) sums 32
            int rb = tid >> 2, rq = tid & 3;
            float ss = 0.f, qq = 0.f;
            #pragma unroll 4
            for (int c = rq * 32; c < rq * 32 + 32; c++) {
                float2 v = __ldcg((const float2*)&g_st[c][rb]);
                ss += v.x; qq += v.y;
            }
            ss += __shfl_xor_sync(0xffffffffu, ss, 1);
            qq += __shfl_xor_sync(0xffffffffu, qq, 1);
            ss += __shfl_xor_sync(0xffffffffu, ss, 2);
            qq += __shfl_xor_sync(0xffffffffu, qq, 2);
            if ((tid & 3) == 0) {
                float mu = ss * (1.f / HD);
                float var = qq * (1.f / HD) - mu * mu;
                s_mu[rb] = mu;
                s_rs[rb] = rsqrtf(var + 1e-5f);
            }
        }
        __syncthreads();

        const float mu = s_mu[b], rs = s_rs[b];
        const int f0 = ph * 4;
        float h0 = tanhf((z01.x - mu) * rs * s_g[f0]     + s_b[f0]);
        float h1 = tanhf((z01.y - mu) * rs * s_g[f0 + 1] + s_b[f0 + 1]);
        float h2 = tanhf((z23.x - mu) * rs * s_g[f0 + 2] + s_b[f0 + 2]);
        float h3 = tanhf((z23.y - mu) * rs * s_g[f0 + 3] + s_b[f0 + 3]);
        if (kh == 0) {
            float4 hv4 = make_float4(h0, h1, h2, h3);
            __stcg((float4*)&g_h[(size_t)b * HD + n0 + f0], hv4);
            *(float4*)&xout[((size_t)b * TS + t) * HD + n0 + f0] = hv4;
        }
        gbar();                                      // h ready for next step
    }
}

// =====================================================================
extern "C" void kernel_launch(void* const* d_in, const int* in_sizes, int n_in,
                              void* d_out, int out_size)
{
    const float* inputs = (const float*)d_in[0];
    const float* Wx     = (const float*)d_in[1];
    const float* bx     = (const float*)d_in[2];
    const float* Wh     = (const float*)d_in[3];
    const float* lng    = (const float*)d_in[4];
    const float* lnb    = (const float*)d_in[5];
    const float* Wy     = (const float*)d_in[6];
    const float* by     = (const float*)d_in[7];

    float* out_x = (float*)d_out;                    // [B,T,H]
    float* out_y = out_x + (size_t)MR * HD;          // [B,T,O]

    float* pA = nullptr; float* pX = nullptr;
    cudaGetSymbolAddress((void**)&pA, g_A);
    cudaGetSymbolAddress((void**)&pX, g_X);

    dim3 ggrid(8, 128);
    const float* xin = inputs;
    for (int l = 0; l < NL; l++) {
        gemm_f2<<<ggrid, 256>>>(xin, Wx + (size_t)l * HD * HD, bx + (size_t)l * HD, pA);
        rst_bar<<<1, 1>>>();
        float* xo = (l == NL - 1) ? out_x : pX;
        recur<<<NCTA, 256>>>(pA, Wh + (size_t)l * HD * HD, lng + (size_t)l * HD,
                             lnb + (size_t)l * HD, xo);
        xin = xo;
    }
    gemm_f2<<<ggrid, 256>>>(out_x, Wy, by, out_y);
}

// round 4
// speedup vs baseline: 3.0866x; 3.0866x over previous
#include <cuda_runtime.h>
#include <cstdint>
#include <cstddef>

#define HD 1024
#define BA 64
#define TS 256
#define NL 4
#define MR (BA*TS)
#define NCTA 128
#define WP 34        // Ws pitch (floats): conflict-free + 8B-aligned pairs

// ---------------- device scratch ----------------
__device__ float    g_A[(size_t)MR * HD];
__device__ float    g_X[(size_t)MR * HD];
__device__ float    g_hT[HD * BA];          // h transposed: [k][b]
__device__ float2   g_st2[32 * BA];         // [ng][b] partial stats
__device__ unsigned g_bar;

typedef unsigned long long ull;

__device__ __forceinline__ void fma2(ull& d, ull a, ull b) {
    asm volatile("fma.rn.f32x2 %0, %1, %2, %0;" : "+l"(d) : "l"(a), "l"(b));
}
__device__ __forceinline__ void add2(ull& d, ull a) {
    asm volatile("add.rn.f32x2 %0, %0, %1;" : "+l"(d) : "l"(a));
}
__device__ __forceinline__ ull splat(float x) {
    ull d; asm("mov.b64 %0, {%1, %1};" : "=l"(d) : "f"(x)); return d;
}
__device__ __forceinline__ float2 unpk(ull v) {
    float2 r; asm("mov.b64 {%0, %1}, %2;" : "=f"(r.x), "=f"(r.y) : "l"(v)); return r;
}
__device__ __forceinline__ unsigned ldacq(unsigned* p) {
    unsigned v; asm volatile("ld.acquire.gpu.u32 %0, [%1];" : "=r"(v) : "l"(p)); return v;
}
__device__ __forceinline__ void redrel(unsigned* p) {
    asm volatile("red.release.gpu.global.add.u32 [%0], 1;" :: "l"(p));
}
__device__ __forceinline__ void cpa16(void* dst, const void* src) {
    uint32_t d = (uint32_t)__cvta_generic_to_shared(dst);
    asm volatile("cp.async.cg.shared.global [%0], [%1], 16;" :: "r"(d), "l"(src));
}

// =====================================================================
// GEMM (unchanged from R3): out = X @ W^T + bias;  M=16384, N=K=1024
// =====================================================================
__global__ __launch_bounds__(256, 2) void gemm_f2(
    const float* __restrict__ X, const float* __restrict__ W,
    const float* __restrict__ bias, float* __restrict__ out)
{
    __shared__ float sA[2][8][128];
    __shared__ float sB[2][8][128];
    const int tid = threadIdx.x;
    const int r = tid >> 1, hf = tid & 1;
    const int ty = tid >> 4, tx = tid & 15;

    const float* xp = X + (size_t)(blockIdx.y * 128 + r) * HD + hf * 4;
    const float* wp = W + (size_t)(blockIdx.x * 128 + r) * HD + hf * 4;

    ull acc[8][4];
    #pragma unroll
    for (int i = 0; i < 8; i++)
        #pragma unroll
        for (int j = 0; j < 4; j++) acc[i][j] = 0ull;

    float4 xa = *(const float4*)xp;
    float4 wa = *(const float4*)wp;
    {
        int kb = hf * 4;
        sA[0][kb+0][r] = xa.x; sA[0][kb+1][r] = xa.y; sA[0][kb+2][r] = xa.z; sA[0][kb+3][r] = xa.w;
        sB[0][kb+0][r] = wa.x; sB[0][kb+1][r] = wa.y; sB[0][kb+2][r] = wa.z; sB[0][kb+3][r] = wa.w;
    }
    __syncthreads();

    for (int c = 0; c < 128; c++) {
        const int cur = c & 1;
        if (c < 127) {
            xa = *(const float4*)(xp + (size_t)(c + 1) * 8);
            wa = *(const float4*)(wp + (size_t)(c + 1) * 8);
        }
        #pragma unroll
        for (int k = 0; k < 8; k++) {
            float4 a0 = *(const float4*)&sA[cur][k][ty * 8];
            float4 a1 = *(const float4*)&sA[cur][k][ty * 8 + 4];
            ulonglong2 b0 = *(const ulonglong2*)&sB[cur][k][tx * 8];
            ulonglong2 b1 = *(const ulonglong2*)&sB[cur][k][tx * 8 + 4];
            ull as[8] = { splat(a0.x), splat(a0.y), splat(a0.z), splat(a0.w),
                          splat(a1.x), splat(a1.y), splat(a1.z), splat(a1.w) };
            #pragma unroll
            for (int i = 0; i < 8; i++) {
                fma2(acc[i][0], as[i], b0.x);
                fma2(acc[i][1], as[i], b0.y);
                fma2(acc[i][2], as[i], b1.x);
                fma2(acc[i][3], as[i], b1.y);
            }
        }
        if (c < 127) {
            int kb = hf * 4, nb = cur ^ 1;
            sA[nb][kb+0][r] = xa.x; sA[nb][kb+1][r] = xa.y; sA[nb][kb+2][r] = xa.z; sA[nb][kb+3][r] = xa.w;
            sB[nb][kb+0][r] = wa.x; sB[nb][kb+1][r] = wa.y; sB[nb][kb+2][r] = wa.z; sB[nb][kb+3][r] = wa.w;
        }
        __syncthreads();
    }

    const size_t m0 = (size_t)blockIdx.y * 128 + ty * 8;
    const int n0 = blockIdx.x * 128 + tx * 8;
    float bl[8];
    #pragma unroll
    for (int j = 0; j < 8; j++) bl[j] = __ldg(bias + n0 + j);
    #pragma unroll
    for (int i = 0; i < 8; i++) {
        float2 p0 = unpk(acc[i][0]), p1 = unpk(acc[i][1]);
        float2 p2 = unpk(acc[i][2]), p3 = unpk(acc[i][3]);
        float4 o0 = make_float4(p0.x + bl[0], p0.y + bl[1], p1.x + bl[2], p1.y + bl[3]);
        float4 o1 = make_float4(p2.x + bl[4], p2.y + bl[5], p3.x + bl[6], p3.y + bl[7]);
        *(float4*)&out[(m0 + i) * HD + n0]     = o0;
        *(float4*)&out[(m0 + i) * HD + n0 + 4] = o1;
    }
}

// =====================================================================
// Recurrence: 128 CTAs = 4 batch-groups x 32 feature-groups.
// CTA: 16 batch rows x 32 features. Wh slice + h slice in SMEM.
// Warp w handles K-chunk [w*128, w*128+128); lane = bo*16 + fh
//   bo (0..1): 8-row half; fh (0..15): feature pair. 8 fma2 per k.
// =====================================================================
__global__ void rst_bar() { g_bar = 0u; }

#define SMEM_DYN ((HD*WP + HD*16) * 4 + 8*16*17*8)

__global__ __launch_bounds__(256, 1) void recur(
    const float* __restrict__ A, const float* __restrict__ Wh,
    const float* __restrict__ lng, const float* __restrict__ lnb,
    float* __restrict__ xout)
{
    extern __shared__ char dsm[];
    float* Ws = (float*)dsm;                       // [1024][WP]
    float* Hs = (float*)(dsm + (size_t)HD*WP*4);   // [1024][16]
    ull*   red = (ull*)(dsm + (size_t)(HD*WP + HD*16)*4); // [8][16][17]
    __shared__ float s_mu[16], s_rs[16], s_g[32], s_b[32];

    const int tid = threadIdx.x, cta = blockIdx.x;
    const int bg = cta >> 5, ng = cta & 31;
    const int B0 = bg * 16, n0 = ng * 32;
    const int w = tid >> 5, lane = tid & 31;
    const int fh = lane & 15, bo = lane >> 4;
    const int b_i = tid >> 4, fp = tid & 15;       // reduction/LN role

    // prologue: Ws[k][f] = Wh[n0+f][k]  (coalesced gmem read)
    for (int i = tid; i < 32 * HD; i += 256) {
        int k = i & 1023, f = i >> 10;
        Ws[k * WP + f] = Wh[(size_t)(n0 + f) * HD + k];
    }
    if (tid < 32) { s_g[tid] = lng[n0 + tid]; s_b[tid] = lnb[n0 + tid]; }
    // zero our g_hT block [n0..n0+32][B0..B0+16]
    if (tid < 128) {
        int rr = tid >> 2, q = tid & 3;
        __stcg((float4*)&g_hT[(n0 + rr) * BA + B0 + q * 4], make_float4(0.f,0.f,0.f,0.f));
    }
    __syncthreads();

    unsigned tgt = 0;
    auto gbar = [&]() {
        __syncthreads();
        tgt += NCTA;
        if (tid == 0) {
            redrel(&g_bar);
            while (ldacq(&g_bar) < tgt) { }
        }
        __syncthreads();
    };
    gbar();   // h zero + everyone's prologue visible

    const int k0 = w * 128;
    float* HsW = Hs + k0 * 16;                     // warp-private chunk

    for (int t = 0; t < TS; t++) {
        // A prefetch for this thread's outputs
        float2 aA = __ldcg((const float2*)&A[((size_t)(B0 + b_i) * TS + t) * HD + n0 + fp * 2]);

        // warp-private cp.async of h chunk: 16 x 16B per lane, 2 groups
        {
            const float* srcb = g_hT + (size_t)k0 * BA + B0;
            #pragma unroll
            for (int j = 0; j < 8; j++) {
                int lin = j * 32 + lane, kl = lin >> 2, q = lin & 3;
                cpa16(HsW + kl * 16 + q * 4, srcb + (size_t)kl * BA + q * 4);
            }
            asm volatile("cp.async.commit_group;");
            #pragma unroll
            for (int j = 8; j < 16; j++) {
                int lin = j * 32 + lane, kl = lin >> 2, q = lin & 3;
                cpa16(HsW + kl * 16 + q * 4, srcb + (size_t)kl * BA + q * 4);
            }
            asm volatile("cp.async.commit_group;");
        }

        ull acc[8];
        #pragma unroll
        for (int j = 0; j < 8; j++) acc[j] = 0ull;

        asm volatile("cp.async.wait_group 1;");
        #pragma unroll 8
        for (int k = k0; k < k0 + 64; k++) {
            ull w2 = *(const ull*)(Ws + (size_t)k * WP + fh * 2);
            float4 h0 = *(const float4*)(Hs + k * 16 + bo * 8);
            float4 h1 = *(const float4*)(Hs + k * 16 + bo * 8 + 4);
            fma2(acc[0], splat(h0.x), w2); fma2(acc[1], splat(h0.y), w2);
            fma2(acc[2], splat(h0.z), w2); fma2(acc[3], splat(h0.w), w2);
            fma2(acc[4], splat(h1.x), w2); fma2(acc[5], splat(h1.y), w2);
            fma2(acc[6], splat(h1.z), w2); fma2(acc[7], splat(h1.w), w2);
        }
        asm volatile("cp.async.wait_group 0;");
        #pragma unroll 8
        for (int k = k0 + 64; k < k0 + 128; k++) {
            ull w2 = *(const ull*)(Ws + (size_t)k * WP + fh * 2);
            float4 h0 = *(const float4*)(Hs + k * 16 + bo * 8);
            float4 h1 = *(const float4*)(Hs + k * 16 + bo * 8 + 4);
            fma2(acc[0], splat(h0.x), w2); fma2(acc[1], splat(h0.y), w2);
            fma2(acc[2], splat(h0.z), w2); fma2(acc[3], splat(h0.w), w2);
            fma2(acc[4], splat(h1.x), w2); fma2(acc[5], splat(h1.y), w2);
            fma2(acc[6], splat(h1.z), w2); fma2(acc[7], splat(h1.w), w2);
        }

        // stash partials: red[w][bo*8+j][fh]
        #pragma unroll
        for (int j = 0; j < 8; j++)
            red[(w * 16 + bo * 8 + j) * 17 + fh] = acc[j];
        __syncthreads();

        // K-reduce over 8 warps: thread (b_i, fp)
        ull z = red[(0 * 16 + b_i) * 17 + fp];
        #pragma unroll
        for (int ww = 1; ww < 8; ww++) add2(z, red[(ww * 16 + b_i) * 17 + fp]);
        float2 z2 = unpk(z);
        z2.x += aA.x; z2.y += aA.y;

        // partial LN stats over our 32 features (16 fp lanes per row)
        float s = z2.x + z2.y;
        float q = z2.x * z2.x + z2.y * z2.y;
        s += __shfl_xor_sync(0xffffffffu, s, 1); q += __shfl_xor_sync(0xffffffffu, q, 1);
        s += __shfl_xor_sync(0xffffffffu, s, 2); q += __shfl_xor_sync(0xffffffffu, q, 2);
        s += __shfl_xor_sync(0xffffffffu, s, 4); q += __shfl_xor_sync(0xffffffffu, q, 4);
        s += __shfl_xor_sync(0xffffffffu, s, 8); q += __shfl_xor_sync(0xffffffffu, q, 8);
        if (fp == 0) __stcg((float2*)&g_st2[ng * BA + B0 + b_i], make_float2(s, q));
        gbar();   // stats ready

        // reduce 32 partials for our 16 rows (threads 0..63)
        if (tid < 64) {
            int rr = tid >> 2, c = tid & 3;
            float ss = 0.f, qq = 0.f;
            #pragma unroll
            for (int m = 0; m < 8; m++) {
                float2 v = __ldcg((const float2*)&g_st2[(c * 8 + m) * BA + B0 + rr]);
                ss += v.x; qq += v.y;
            }
            ss += __shfl_xor_sync(0xffffffffu, ss, 1); qq += __shfl_xor_sync(0xffffffffu, qq, 1);
            ss += __shfl_xor_sync(0xffffffffu, ss, 2); qq += __shfl_xor_sync(0xffffffffu, qq, 2);
            if (c == 0) {
                float mu = ss * (1.f / HD);
                float var = qq * (1.f / HD) - mu * mu;
                s_mu[rr] = mu;
                s_rs[rr] = rsqrtf(var + 1e-5f);
            }
        }
        __syncthreads();

        const float mu = s_mu[b_i], rs = s_rs[b_i];
        const int f = fp * 2;
        float h0 = tanhf((z2.x - mu) * rs * s_g[f]     + s_b[f]);
        float h1 = tanhf((z2.y - mu) * rs * s_g[f + 1] + s_b[f + 1]);
        *(float2*)&xout[((size_t)(B0 + b_i) * TS + t) * HD + n0 + f] = make_float2(h0, h1);
        __stcg(&g_hT[(n0 + f) * BA + B0 + b_i], h0);
        __stcg(&g_hT[(n0 + f + 1) * BA + B0 + b_i], h1);
        gbar();   // h ready for next step
    }
}

// =====================================================================
extern "C" void kernel_launch(void* const* d_in, const int* in_sizes, int n_in,
                              void* d_out, int out_size)
{
    const float* inputs = (const float*)d_in[0];
    const float* Wx     = (const float*)d_in[1];
    const float* bx     = (const float*)d_in[2];
    const float* Wh     = (const float*)d_in[3];
    const float* lng    = (const float*)d_in[4];
    const float* lnb    = (const float*)d_in[5];
    const float* Wy     = (const float*)d_in[6];
    const float* by     = (const float*)d_in[7];

    float* out_x = (float*)d_out;
    float* out_y = out_x + (size_t)MR * HD;

    float* pA = nullptr; float* pX = nullptr;
    cudaGetSymbolAddress((void**)&pA, g_A);
    cudaGetSymbolAddress((void**)&pX, g_X);

    cudaFuncSetAttribute(recur, cudaFuncAttributeMaxDynamicSharedMemorySize, SMEM_DYN);

    dim3 ggrid(8, 128);
    const float* xin = inputs;
    for (int l = 0; l < NL; l++) {
        gemm_f2<<<ggrid, 256>>>(xin, Wx + (size_t)l * HD * HD, bx + (size_t)l * HD, pA);
        rst_bar<<<1, 1>>>();
        float* xo = (l == NL - 1) ? out_x : pX;
        recur<<<NCTA, 256, SMEM_DYN>>>(pA, Wh + (size_t)l * HD * HD,
                                       lng + (size_t)l * HD, lnb + (size_t)l * HD, xo);
        xin = xo;
    }
    gemm_f2<<<ggrid, 256>>>(out_x, Wy, by, out_y);
}